// round 1
// baseline (speedup 1.0000x reference)
#include <cuda_runtime.h>
#include <math.h>

#define B_   2
#define S_   2048
#define HID_ 2048
#define NH_  16
#define HD_  128
#define KDIM 2048

// Scratch (static device allocations are the allowed mechanism)
__device__ float g_qkv[(size_t)3 * B_ * NH_ * S_ * HD_];   // [which][b][h][s][d]  96MB
__device__ float g_ctx[(size_t)B_ * S_ * HID_];            // [b][s][h][d] = [m][2048]  32MB

// ---------------------------------------------------------------------------
// Tiled SGEMM: C[m][n] = sum_k A[m][k] * W[n][k]   (both K-contiguous)
// BM=BN=128, BK=16, 256 threads, 8x8 micro-tile.
// MODE 0: A = x param, scatter-write q/k/v into g_qkv ([which][b][h][s][d])
// MODE 1: A = g_ctx, write Cout row-major [M][2048]
// ---------------------------------------------------------------------------
template <int MODE>
__global__ __launch_bounds__(256)
void gemm_kernel(const float* __restrict__ Ain,
                 const float* __restrict__ W,
                 float* __restrict__ Cout) {
    const int m0 = blockIdx.y * 128;
    const int n0 = blockIdx.x * 128;
    const int tid = threadIdx.x;
    const int tx = tid & 15;
    const int ty = tid >> 4;

    const float* A = (MODE == 0) ? Ain : g_ctx;

    __shared__ float As[16 * 128];
    __shared__ float Bs[16 * 128];

    float acc[8][8];
#pragma unroll
    for (int i = 0; i < 8; i++)
#pragma unroll
        for (int j = 0; j < 8; j++) acc[i][j] = 0.f;

    for (int k0 = 0; k0 < KDIM; k0 += 16) {
#pragma unroll
        for (int t = 0; t < 2; t++) {
            int l = tid + t * 256;          // 0..511
            int row = l >> 2;               // 0..127
            int kc = (l & 3) << 2;          // 0,4,8,12
            float4 av = *(const float4*)&A[(size_t)(m0 + row) * KDIM + k0 + kc];
            As[(kc + 0) * 128 + row] = av.x;
            As[(kc + 1) * 128 + row] = av.y;
            As[(kc + 2) * 128 + row] = av.z;
            As[(kc + 3) * 128 + row] = av.w;
            float4 bv = *(const float4*)&W[(size_t)(n0 + row) * KDIM + k0 + kc];
            Bs[(kc + 0) * 128 + row] = bv.x;
            Bs[(kc + 1) * 128 + row] = bv.y;
            Bs[(kc + 2) * 128 + row] = bv.z;
            Bs[(kc + 3) * 128 + row] = bv.w;
        }
        __syncthreads();
#pragma unroll
        for (int kk = 0; kk < 16; kk++) {
            float4 a0 = *(float4*)&As[kk * 128 + ty * 4];
            float4 a1 = *(float4*)&As[kk * 128 + 64 + ty * 4];
            float4 b0 = *(float4*)&Bs[kk * 128 + tx * 4];
            float4 b1 = *(float4*)&Bs[kk * 128 + 64 + tx * 4];
            float ar[8] = {a0.x, a0.y, a0.z, a0.w, a1.x, a1.y, a1.z, a1.w};
            float br[8] = {b0.x, b0.y, b0.z, b0.w, b1.x, b1.y, b1.z, b1.w};
#pragma unroll
            for (int i = 0; i < 8; i++)
#pragma unroll
                for (int j = 0; j < 8; j++) acc[i][j] += ar[i] * br[j];
        }
        __syncthreads();
    }

    // epilogue
#pragma unroll
    for (int i = 0; i < 8; i++) {
        int gm = m0 + ((i < 4) ? (ty * 4 + i) : (64 + ty * 4 + (i - 4)));
#pragma unroll
        for (int jj = 0; jj < 2; jj++) {
            int gn = n0 + jj * 64 + tx * 4;
            float4 v = make_float4(acc[i][jj * 4 + 0], acc[i][jj * 4 + 1],
                                   acc[i][jj * 4 + 2], acc[i][jj * 4 + 3]);
            if (MODE == 0) {
                int which = gn / HID_;
                int rem = gn % HID_;
                int h = rem / HD_;
                int d = rem % HD_;
                int b = gm / S_;
                int s = gm % S_;
                size_t off = (size_t)which * ((size_t)B_ * NH_ * S_ * HD_) +
                             (((size_t)(b * NH_ + h)) * S_ + s) * HD_ + d;
                *(float4*)&g_qkv[off] = v;
            } else {
                *(float4*)&Cout[(size_t)gm * HID_ + gn] = v;
            }
        }
    }
}

// ---------------------------------------------------------------------------
// RoPE in-place on Q and K halves of g_qkv.
// ---------------------------------------------------------------------------
__global__ __launch_bounds__(256)
void rope_kernel(const float* __restrict__ cosT, const float* __restrict__ sinT) {
    long long t = (long long)blockIdx.x * 256 + threadIdx.x;  // 0 .. 2*B*NH*S*64-1
    int d = (int)(t & 63);
    long long row = t >> 6;            // over [which(0,1)][b][h][s]
    int s = (int)(row % S_);
    float* p = g_qkv + row * HD_;
    float x1 = p[d];
    float x2 = p[d + 64];
    float c1 = cosT[s * HD_ + d];
    float s1 = sinT[s * HD_ + d];
    float c2 = cosT[s * HD_ + d + 64];
    float s2 = sinT[s * HD_ + d + 64];
    p[d]      = x1 * c1 - x2 * s1;
    p[d + 64] = x2 * c2 + x1 * s2;
}

// ---------------------------------------------------------------------------
// Causal flash attention, fp32. BQ=BK=64, 256 threads.
// grid = (S/64, B*NH). Writes ctx in [b][s][h][d] layout.
// ---------------------------------------------------------------------------
#define BQ 64
#define BK 64
#define ATTN_SMEM (28672 * 4)   // sQt(8192)+sKt(8192)+sV(8192)+sP(4096) floats

__global__ __launch_bounds__(256)
void attn_kernel() {
    extern __shared__ float sm[];
    float* sQt = sm;             // [128][64] transposed
    float* sKt = sm + 8192;      // [128][64] transposed
    float* sV  = sm + 16384;     // [64][128]
    float* sP  = sm + 24576;     // [64][64]

    const int qt = blockIdx.x;
    const int bh = blockIdx.y;
    const int b = bh / NH_;
    const int h = bh % NH_;
    const int q0 = qt * BQ;

    const size_t head_stride = (size_t)S_ * HD_;
    const float* Q = g_qkv + (size_t)bh * head_stride;
    const float* Kp = g_qkv + (size_t)(B_ * NH_) * head_stride + (size_t)bh * head_stride;
    const float* Vp = g_qkv + 2 * (size_t)(B_ * NH_) * head_stride + (size_t)bh * head_stride;

    const int tid = threadIdx.x;
    const int tx = tid & 15;     // col group
    const int ty = tid >> 4;     // row group (0..15)

    // load Q tile (transposed)
#pragma unroll
    for (int t = 0; t < 8; t++) {
        int lf = tid + t * 256;          // 0..2047
        int r = lf >> 5;                 // 0..63
        int dc = (lf & 31) << 2;         // 0..124
        float4 v = *(const float4*)&Q[(size_t)(q0 + r) * HD_ + dc];
        sQt[(dc + 0) * 64 + r] = v.x;
        sQt[(dc + 1) * 64 + r] = v.y;
        sQt[(dc + 2) * 64 + r] = v.z;
        sQt[(dc + 3) * 64 + r] = v.w;
    }

    float m_[4], l_[4];
    float4 O[4][2];
#pragma unroll
    for (int i = 0; i < 4; i++) {
        m_[i] = -1e30f;
        l_[i] = 0.f;
        O[i][0] = make_float4(0.f, 0.f, 0.f, 0.f);
        O[i][1] = make_float4(0.f, 0.f, 0.f, 0.f);
    }
    __syncthreads();

    const float sc = 0.08838834764831845f;  // 1/sqrt(128)

    for (int kt = 0; kt <= qt; kt++) {
        const int k0 = kt * BK;
        // load K (transposed) and V (natural)
#pragma unroll
        for (int t = 0; t < 8; t++) {
            int lf = tid + t * 256;
            int r = lf >> 5;
            int dc = (lf & 31) << 2;
            float4 kv = *(const float4*)&Kp[(size_t)(k0 + r) * HD_ + dc];
            sKt[(dc + 0) * 64 + r] = kv.x;
            sKt[(dc + 1) * 64 + r] = kv.y;
            sKt[(dc + 2) * 64 + r] = kv.z;
            sKt[(dc + 3) * 64 + r] = kv.w;
            *(float4*)&sV[r * HD_ + dc] = *(const float4*)&Vp[(size_t)(k0 + r) * HD_ + dc];
        }
        __syncthreads();

        // S = Q K^T (4x4 micro)
        float s4[4][4];
#pragma unroll
        for (int i = 0; i < 4; i++)
#pragma unroll
            for (int j = 0; j < 4; j++) s4[i][j] = 0.f;

#pragma unroll 4
        for (int d = 0; d < HD_; d++) {
            float4 q4 = *(float4*)&sQt[d * 64 + ty * 4];
            float4 k4 = *(float4*)&sKt[d * 64 + tx * 4];
            float qv[4] = {q4.x, q4.y, q4.z, q4.w};
            float kv[4] = {k4.x, k4.y, k4.z, k4.w};
#pragma unroll
            for (int i = 0; i < 4; i++)
#pragma unroll
                for (int j = 0; j < 4; j++) s4[i][j] += qv[i] * kv[j];
        }

        const bool diag = (kt == qt);
#pragma unroll
        for (int i = 0; i < 4; i++) {
#pragma unroll
            for (int j = 0; j < 4; j++) {
                s4[i][j] *= sc;
                if (diag && (k0 + tx * 4 + j > q0 + ty * 4 + i)) s4[i][j] = -1e9f;
            }
        }

        // online softmax
#pragma unroll
        for (int i = 0; i < 4; i++) {
            float tm = fmaxf(fmaxf(s4[i][0], s4[i][1]), fmaxf(s4[i][2], s4[i][3]));
#pragma unroll
            for (int off = 8; off > 0; off >>= 1)
                tm = fmaxf(tm, __shfl_xor_sync(0xffffffffu, tm, off));
            float mn = fmaxf(m_[i], tm);
            float al = __expf(m_[i] - mn);
            float rs = 0.f;
#pragma unroll
            for (int j = 0; j < 4; j++) {
                s4[i][j] = __expf(s4[i][j] - mn);
                rs += s4[i][j];
            }
#pragma unroll
            for (int off = 8; off > 0; off >>= 1)
                rs += __shfl_xor_sync(0xffffffffu, rs, off);
            l_[i] = l_[i] * al + rs;
            m_[i] = mn;
            O[i][0].x *= al; O[i][0].y *= al; O[i][0].z *= al; O[i][0].w *= al;
            O[i][1].x *= al; O[i][1].y *= al; O[i][1].z *= al; O[i][1].w *= al;
            *(float4*)&sP[(ty * 4 + i) * 64 + tx * 4] =
                make_float4(s4[i][0], s4[i][1], s4[i][2], s4[i][3]);
        }
        __syncthreads();

        // O += P V
#pragma unroll 2
        for (int j = 0; j < BK; j++) {
            float4 v0 = *(float4*)&sV[j * HD_ + tx * 8];
            float4 v1 = *(float4*)&sV[j * HD_ + tx * 8 + 4];
#pragma unroll
            for (int i = 0; i < 4; i++) {
                float pv = sP[(ty * 4 + i) * 64 + j];
                O[i][0].x += pv * v0.x; O[i][0].y += pv * v0.y;
                O[i][0].z += pv * v0.z; O[i][0].w += pv * v0.w;
                O[i][1].x += pv * v1.x; O[i][1].y += pv * v1.y;
                O[i][1].z += pv * v1.z; O[i][1].w += pv * v1.w;
            }
        }
        __syncthreads();
    }

    // normalize + write ctx as [b][s][h][d]
#pragma unroll
    for (int i = 0; i < 4; i++) {
        float inv = 1.f / l_[i];
        int srow = q0 + ty * 4 + i;
        size_t base = (((size_t)b * S_ + srow) * NH_ + h) * HD_ + tx * 8;
        float4 o0 = make_float4(O[i][0].x * inv, O[i][0].y * inv, O[i][0].z * inv, O[i][0].w * inv);
        float4 o1 = make_float4(O[i][1].x * inv, O[i][1].y * inv, O[i][1].z * inv, O[i][1].w * inv);
        *(float4*)&g_ctx[base] = o0;
        *(float4*)&g_ctx[base + 4] = o1;
    }
}

// ---------------------------------------------------------------------------
extern "C" void kernel_launch(void* const* d_in, const int* in_sizes, int n_in,
                              void* d_out, int out_size) {
    (void)in_sizes; (void)n_in; (void)out_size;
    const float* x     = (const float*)d_in[0];
    const float* w_qkv = (const float*)d_in[1];
    const float* w_o   = (const float*)d_in[2];
    const float* cosT  = (const float*)d_in[3];
    const float* sinT  = (const float*)d_in[4];
    float* out = (float*)d_out;

    cudaFuncSetAttribute(attn_kernel, cudaFuncAttributeMaxDynamicSharedMemorySize, ATTN_SMEM);

    // 1) QKV projection: M=4096, N=6144
    gemm_kernel<0><<<dim3(6144 / 128, 4096 / 128), 256>>>(x, w_qkv, nullptr);

    // 2) RoPE on Q and K
    rope_kernel<<<(2 * B_ * NH_ * S_ * 64) / 256, 256>>>(cosT, sinT);

    // 3) Flash attention
    attn_kernel<<<dim3(S_ / BQ, B_ * NH_), 256, ATTN_SMEM>>>();

    // 4) Output projection: M=4096, N=2048
    gemm_kernel<1><<<dim3(2048 / 128, 4096 / 128), 256>>>(nullptr, w_o, out);
}

// round 3
// speedup vs baseline: 1.2856x; 1.2856x over previous
#include <cuda_runtime.h>
#include <cuda_bf16.h>
#include <cstdint>
#include <math.h>

#define B_   2
#define S_   2048
#define HID_ 2048
#define NH_  16
#define HD_  128
#define KDIM 2048

__device__ float g_qkv[(size_t)3 * B_ * NH_ * S_ * HD_];   // [which][b][h][s][d]
__device__ float g_ctx[(size_t)B_ * S_ * HID_];            // [b][s][h][d] row-major [M][2048]

// ---------------------------------------------------------------------------
// Split-bf16 tensor-core GEMM: C[m][n] = sum_k A[m][k] * W[n][k]
// BM=BN=128, BK=32, 256 threads = 8 warps (4 Mwarps x 2 Nwarps),
// warp tile 32x64 via m16n8k16 (2 Mtiles x 8 Ntiles).
// fp32 emulation: A=Ah+Al, B=Bh+Bl (bf16), D += Ah*Bh + Al*Bh + Ah*Bl.
// MODE 0: A = x, scatter q/k/v into g_qkv.  MODE 1: A = g_ctx, write Cout.
// ---------------------------------------------------------------------------
#define SMSTRIDE 40   // bf16 elems per row (32 + 8 pad) = 20 words -> conflict-free frags

#define MMA_BF16(d, a, b)                                                     \
    asm volatile(                                                             \
        "mma.sync.aligned.m16n8k16.row.col.f32.bf16.bf16.f32 "                \
        "{%0,%1,%2,%3}, {%4,%5,%6,%7}, {%8,%9}, {%0,%1,%2,%3};\n"             \
        : "+f"((d)[0]), "+f"((d)[1]), "+f"((d)[2]), "+f"((d)[3])              \
        : "r"((a)[0]), "r"((a)[1]), "r"((a)[2]), "r"((a)[3]),                 \
          "r"((b)[0]), "r"((b)[1]))

template <int MODE>
__global__ __launch_bounds__(256)
void gemm_bf16_kernel(const float* __restrict__ Ain,
                      const float* __restrict__ W,
                      float* __restrict__ Cout) {
    const int m0 = blockIdx.y * 128;
    const int n0 = blockIdx.x * 128;
    const int tid = threadIdx.x;
    const int lane = tid & 31;
    const int warp = tid >> 5;
    const int warpM = warp & 3;   // 0..3 -> 32 rows each
    const int warpN = warp >> 2;  // 0..1 -> 64 cols each

    const float* A = (MODE == 0) ? Ain : g_ctx;

    __shared__ __nv_bfloat16 Ah[128 * SMSTRIDE];
    __shared__ __nv_bfloat16 Al[128 * SMSTRIDE];
    __shared__ __nv_bfloat16 Bh[128 * SMSTRIDE];
    __shared__ __nv_bfloat16 Bl[128 * SMSTRIDE];

    float C[2][8][4];
#pragma unroll
    for (int mt = 0; mt < 2; mt++)
#pragma unroll
        for (int nt = 0; nt < 8; nt++)
#pragma unroll
            for (int r = 0; r < 4; r++) C[mt][nt][r] = 0.f;

    const uint32_t* Ahw = (const uint32_t*)Ah;
    const uint32_t* Alw = (const uint32_t*)Al;
    const uint32_t* Bhw = (const uint32_t*)Bh;
    const uint32_t* Blw = (const uint32_t*)Bl;

    const int g = lane >> 2;       // group id 0..7
    const int qp = lane & 3;       // quad pair 0..3

    for (int k0 = 0; k0 < KDIM; k0 += 32) {
        // ---- load fp32 tiles, split into hi/lo bf16, store to smem ----
#pragma unroll
        for (int t = 0; t < 4; t++) {
            int l = tid + t * 256;      // 0..1023
            int row = l >> 3;           // 0..127
            int kc = (l & 7) * 4;       // 0..28
            float4 av = *(const float4*)&A[(size_t)(m0 + row) * KDIM + k0 + kc];
            float4 bv = *(const float4*)&W[(size_t)(n0 + row) * KDIM + k0 + kc];
            float af[4] = {av.x, av.y, av.z, av.w};
            float bf[4] = {bv.x, bv.y, bv.z, bv.w};
#pragma unroll
            for (int e = 0; e < 4; e++) {
                __nv_bfloat16 ah = __float2bfloat16(af[e]);
                __nv_bfloat16 al = __float2bfloat16(af[e] - __bfloat162float(ah));
                __nv_bfloat16 bh = __float2bfloat16(bf[e]);
                __nv_bfloat16 bl = __float2bfloat16(bf[e] - __bfloat162float(bh));
                Ah[row * SMSTRIDE + kc + e] = ah;
                Al[row * SMSTRIDE + kc + e] = al;
                Bh[row * SMSTRIDE + kc + e] = bh;
                Bl[row * SMSTRIDE + kc + e] = bl;
            }
        }
        __syncthreads();

        // ---- MMAs over 2 k16 chunks ----
#pragma unroll
        for (int kc = 0; kc < 2; kc++) {
            const int kw = kc * 8 + qp;   // word col for k-low pair; +4 for k-high
            uint32_t a_hi[2][4], a_lo[2][4];
#pragma unroll
            for (int mt = 0; mt < 2; mt++) {
                int r0 = warpM * 32 + mt * 16 + g;   // rows g and g+8
                int w0 = r0 * (SMSTRIDE / 2) + kw;
                int w1 = (r0 + 8) * (SMSTRIDE / 2) + kw;
                a_hi[mt][0] = Ahw[w0];
                a_hi[mt][1] = Ahw[w1];
                a_hi[mt][2] = Ahw[w0 + 4];
                a_hi[mt][3] = Ahw[w1 + 4];
                a_lo[mt][0] = Alw[w0];
                a_lo[mt][1] = Alw[w1];
                a_lo[mt][2] = Alw[w0 + 4];
                a_lo[mt][3] = Alw[w1 + 4];
            }
#pragma unroll
            for (int nt = 0; nt < 8; nt++) {
                int nr = warpN * 64 + nt * 8 + g;
                int wb = nr * (SMSTRIDE / 2) + kw;
                uint32_t b_hi[2], b_lo[2];
                b_hi[0] = Bhw[wb];
                b_hi[1] = Bhw[wb + 4];
                b_lo[0] = Blw[wb];
                b_lo[1] = Blw[wb + 4];
#pragma unroll
                for (int mt = 0; mt < 2; mt++) {
                    MMA_BF16(C[mt][nt], a_hi[mt], b_hi);
                    MMA_BF16(C[mt][nt], a_lo[mt], b_hi);
                    MMA_BF16(C[mt][nt], a_hi[mt], b_lo);
                }
            }
        }
        __syncthreads();
    }

    // ---- epilogue ----
#pragma unroll
    for (int mt = 0; mt < 2; mt++) {
#pragma unroll
        for (int nt = 0; nt < 8; nt++) {
            int gm0 = m0 + warpM * 32 + mt * 16 + g;
            int gn = n0 + warpN * 64 + nt * 8 + qp * 2;
            float2 v0 = make_float2(C[mt][nt][0], C[mt][nt][1]);
            float2 v1 = make_float2(C[mt][nt][2], C[mt][nt][3]);
            if (MODE == 0) {
                int which = gn >> 11;
                int rem = gn & 2047;
                int h = rem >> 7;
                int d = rem & 127;
#pragma unroll
                for (int rr = 0; rr < 2; rr++) {
                    int gm = gm0 + rr * 8;
                    int b = gm >> 11;
                    int s = gm & 2047;
                    size_t off = (size_t)which * ((size_t)B_ * NH_ * S_ * HD_) +
                                 (((size_t)(b * NH_ + h)) * S_ + s) * HD_ + d;
                    *(float2*)&g_qkv[off] = rr ? v1 : v0;
                }
            } else {
                *(float2*)&Cout[(size_t)gm0 * HID_ + gn] = v0;
                *(float2*)&Cout[(size_t)(gm0 + 8) * HID_ + gn] = v1;
            }
        }
    }
}

// ---------------------------------------------------------------------------
// RoPE in-place on Q and K halves of g_qkv.
// ---------------------------------------------------------------------------
__global__ __launch_bounds__(256)
void rope_kernel(const float* __restrict__ cosT, const float* __restrict__ sinT) {
    long long t = (long long)blockIdx.x * 256 + threadIdx.x;
    int d = (int)(t & 63);
    long long row = t >> 6;
    int s = (int)(row % S_);
    float* p = g_qkv + row * HD_;
    float x1 = p[d];
    float x2 = p[d + 64];
    float c1 = cosT[s * HD_ + d];
    float s1 = sinT[s * HD_ + d];
    float c2 = cosT[s * HD_ + d + 64];
    float s2 = sinT[s * HD_ + d + 64];
    p[d]      = x1 * c1 - x2 * s1;
    p[d + 64] = x2 * c2 + x1 * s2;
}

// ---------------------------------------------------------------------------
// Causal flash attention, fp32 SIMT. BQ=BK=64, 256 threads.
// ---------------------------------------------------------------------------
#define BQ 64
#define BK 64
#define ATTN_SMEM (28672 * 4)

__global__ __launch_bounds__(256)
void attn_kernel() {
    extern __shared__ float sm[];
    float* sQt = sm;
    float* sKt = sm + 8192;
    float* sV  = sm + 16384;
    float* sP  = sm + 24576;

    const int qt = blockIdx.x;
    const int bh = blockIdx.y;
    const int b = bh / NH_;
    const int h = bh % NH_;
    const int q0 = qt * BQ;

    const size_t head_stride = (size_t)S_ * HD_;
    const float* Q = g_qkv + (size_t)bh * head_stride;
    const float* Kp = g_qkv + (size_t)(B_ * NH_) * head_stride + (size_t)bh * head_stride;
    const float* Vp = g_qkv + 2 * (size_t)(B_ * NH_) * head_stride + (size_t)bh * head_stride;

    const int tid = threadIdx.x;
    const int tx = tid & 15;
    const int ty = tid >> 4;

#pragma unroll
    for (int t = 0; t < 8; t++) {
        int lf = tid + t * 256;
        int r = lf >> 5;
        int dc = (lf & 31) << 2;
        float4 v = *(const float4*)&Q[(size_t)(q0 + r) * HD_ + dc];
        sQt[(dc + 0) * 64 + r] = v.x;
        sQt[(dc + 1) * 64 + r] = v.y;
        sQt[(dc + 2) * 64 + r] = v.z;
        sQt[(dc + 3) * 64 + r] = v.w;
    }

    float m_[4], l_[4];
    float4 O[4][2];
#pragma unroll
    for (int i = 0; i < 4; i++) {
        m_[i] = -1e30f;
        l_[i] = 0.f;
        O[i][0] = make_float4(0.f, 0.f, 0.f, 0.f);
        O[i][1] = make_float4(0.f, 0.f, 0.f, 0.f);
    }
    __syncthreads();

    const float sc = 0.08838834764831845f;

    for (int kt = 0; kt <= qt; kt++) {
        const int k0 = kt * BK;
#pragma unroll
        for (int t = 0; t < 8; t++) {
            int lf = tid + t * 256;
            int r = lf >> 5;
            int dc = (lf & 31) << 2;
            float4 kv = *(const float4*)&Kp[(size_t)(k0 + r) * HD_ + dc];
            sKt[(dc + 0) * 64 + r] = kv.x;
            sKt[(dc + 1) * 64 + r] = kv.y;
            sKt[(dc + 2) * 64 + r] = kv.z;
            sKt[(dc + 3) * 64 + r] = kv.w;
            *(float4*)&sV[r * HD_ + dc] = *(const float4*)&Vp[(size_t)(k0 + r) * HD_ + dc];
        }
        __syncthreads();

        float s4[4][4];
#pragma unroll
        for (int i = 0; i < 4; i++)
#pragma unroll
            for (int j = 0; j < 4; j++) s4[i][j] = 0.f;

#pragma unroll 4
        for (int d = 0; d < HD_; d++) {
            float4 q4 = *(float4*)&sQt[d * 64 + ty * 4];
            float4 k4 = *(float4*)&sKt[d * 64 + tx * 4];
            float qv[4] = {q4.x, q4.y, q4.z, q4.w};
            float kv[4] = {k4.x, k4.y, k4.z, k4.w};
#pragma unroll
            for (int i = 0; i < 4; i++)
#pragma unroll
                for (int j = 0; j < 4; j++) s4[i][j] += qv[i] * kv[j];
        }

        const bool diag = (kt == qt);
#pragma unroll
        for (int i = 0; i < 4; i++) {
#pragma unroll
            for (int j = 0; j < 4; j++) {
                s4[i][j] *= sc;
                if (diag && (k0 + tx * 4 + j > q0 + ty * 4 + i)) s4[i][j] = -1e9f;
            }
        }

#pragma unroll
        for (int i = 0; i < 4; i++) {
            float tm = fmaxf(fmaxf(s4[i][0], s4[i][1]), fmaxf(s4[i][2], s4[i][3]));
#pragma unroll
            for (int off = 8; off > 0; off >>= 1)
                tm = fmaxf(tm, __shfl_xor_sync(0xffffffffu, tm, off));
            float mn = fmaxf(m_[i], tm);
            float al = __expf(m_[i] - mn);
            float rs = 0.f;
#pragma unroll
            for (int j = 0; j < 4; j++) {
                s4[i][j] = __expf(s4[i][j] - mn);
                rs += s4[i][j];
            }
#pragma unroll
            for (int off = 8; off > 0; off >>= 1)
                rs += __shfl_xor_sync(0xffffffffu, rs, off);
            l_[i] = l_[i] * al + rs;
            m_[i] = mn;
            O[i][0].x *= al; O[i][0].y *= al; O[i][0].z *= al; O[i][0].w *= al;
            O[i][1].x *= al; O[i][1].y *= al; O[i][1].z *= al; O[i][1].w *= al;
            *(float4*)&sP[(ty * 4 + i) * 64 + tx * 4] =
                make_float4(s4[i][0], s4[i][1], s4[i][2], s4[i][3]);
        }
        __syncthreads();

#pragma unroll 2
        for (int j = 0; j < BK; j++) {
            float4 v0 = *(float4*)&sV[j * HD_ + tx * 8];
            float4 v1 = *(float4*)&sV[j * HD_ + tx * 8 + 4];
#pragma unroll
            for (int i = 0; i < 4; i++) {
                float pv = sP[(ty * 4 + i) * 64 + j];
                O[i][0].x += pv * v0.x; O[i][0].y += pv * v0.y;
                O[i][0].z += pv * v0.z; O[i][0].w += pv * v0.w;
                O[i][1].x += pv * v1.x; O[i][1].y += pv * v1.y;
                O[i][1].z += pv * v1.z; O[i][1].w += pv * v1.w;
            }
        }
        __syncthreads();
    }

#pragma unroll
    for (int i = 0; i < 4; i++) {
        float inv = 1.f / l_[i];
        int srow = q0 + ty * 4 + i;
        size_t base = (((size_t)b * S_ + srow) * NH_ + h) * HD_ + tx * 8;
        float4 o0 = make_float4(O[i][0].x * inv, O[i][0].y * inv, O[i][0].z * inv, O[i][0].w * inv);
        float4 o1 = make_float4(O[i][1].x * inv, O[i][1].y * inv, O[i][1].z * inv, O[i][1].w * inv);
        *(float4*)&g_ctx[base] = o0;
        *(float4*)&g_ctx[base + 4] = o1;
    }
}

// ---------------------------------------------------------------------------
extern "C" void kernel_launch(void* const* d_in, const int* in_sizes, int n_in,
                              void* d_out, int out_size) {
    (void)in_sizes; (void)n_in; (void)out_size;
    const float* x     = (const float*)d_in[0];
    const float* w_qkv = (const float*)d_in[1];
    const float* w_o   = (const float*)d_in[2];
    const float* cosT  = (const float*)d_in[3];
    const float* sinT  = (const float*)d_in[4];
    float* out = (float*)d_out;

    cudaFuncSetAttribute(attn_kernel, cudaFuncAttributeMaxDynamicSharedMemorySize, ATTN_SMEM);

    // 1) QKV projection: M=4096, N=6144 (tensor cores, split-bf16)
    gemm_bf16_kernel<0><<<dim3(6144 / 128, 4096 / 128), 256>>>(x, w_qkv, nullptr);

    // 2) RoPE on Q and K
    rope_kernel<<<(2 * B_ * NH_ * S_ * 64) / 256, 256>>>(cosT, sinT);

    // 3) Flash attention
    attn_kernel<<<dim3(S_ / BQ, B_ * NH_), 256, ATTN_SMEM>>>();

    // 4) Output projection: M=4096, N=2048 (tensor cores, split-bf16)
    gemm_bf16_kernel<1><<<dim3(2048 / 128, 4096 / 128), 256>>>(nullptr, w_o, out);
}

// round 4
// speedup vs baseline: 2.7534x; 2.1417x over previous
#include <cuda_runtime.h>
#include <cuda_bf16.h>
#include <cstdint>
#include <math.h>

#define B_   2
#define S_   2048
#define HID_ 2048
#define NH_  16
#define HD_  128
#define KDIM 2048

__device__ float g_qkv[(size_t)3 * B_ * NH_ * S_ * HD_];   // [which][b][h][s][d]
__device__ float g_ctx[(size_t)B_ * S_ * HID_];            // [b][s][h][d] row-major [M][2048]

// ---------------- common helpers ----------------
__device__ __forceinline__ uint32_t s2u(const void* p) {
    return (uint32_t)__cvta_generic_to_shared(p);
}
// pack (lo, hi) floats -> bf16x2 (lo in low half)
__device__ __forceinline__ uint32_t packbf(float lo, float hi) {
    uint32_t r;
    asm("cvt.rn.bf16x2.f32 %0, %1, %2;" : "=r"(r) : "f"(hi), "f"(lo));
    return r;
}

#define MMA_BF16(d, a, b)                                                     \
    asm volatile(                                                             \
        "mma.sync.aligned.m16n8k16.row.col.f32.bf16.bf16.f32 "                \
        "{%0,%1,%2,%3}, {%4,%5,%6,%7}, {%8,%9}, {%0,%1,%2,%3};\n"             \
        : "+f"((d)[0]), "+f"((d)[1]), "+f"((d)[2]), "+f"((d)[3])              \
        : "r"((a)[0]), "r"((a)[1]), "r"((a)[2]), "r"((a)[3]),                 \
          "r"((b)[0]), "r"((b)[1]))

#define LDSM_X4(r, addr)                                                      \
    asm volatile("ldmatrix.sync.aligned.m8n8.x4.shared.b16 {%0,%1,%2,%3}, [%4];" \
                 : "=r"((r)[0]), "=r"((r)[1]), "=r"((r)[2]), "=r"((r)[3])     \
                 : "r"(addr))

#define LDSM_X4T(r, addr)                                                     \
    asm volatile("ldmatrix.sync.aligned.m8n8.x4.trans.shared.b16 {%0,%1,%2,%3}, [%4];" \
                 : "=r"((r)[0]), "=r"((r)[1]), "=r"((r)[2]), "=r"((r)[3])     \
                 : "r"(addr))

// ---------------------------------------------------------------------------
// Split-bf16 tensor-core GEMM with ldmatrix fragment loads.
// C[m][n] = sum_k A[m][k]*W[n][k]. BM=BN=128, BK=32, 256 thr, 8 warps (4Mx2N).
// ---------------------------------------------------------------------------
#define SMSTRIDE 40

template <int MODE>
__global__ __launch_bounds__(256, 2)
void gemm_bf16_kernel(const float* __restrict__ Ain,
                      const float* __restrict__ W,
                      float* __restrict__ Cout) {
    const int m0 = blockIdx.y * 128;
    const int n0 = blockIdx.x * 128;
    const int tid = threadIdx.x;
    const int lane = tid & 31;
    const int warp = tid >> 5;
    const int warpM = warp & 3;
    const int warpN = warp >> 2;

    const float* A = (MODE == 0) ? Ain : g_ctx;

    __shared__ __nv_bfloat16 Ah[128 * SMSTRIDE];
    __shared__ __nv_bfloat16 Al[128 * SMSTRIDE];
    __shared__ __nv_bfloat16 Bh[128 * SMSTRIDE];
    __shared__ __nv_bfloat16 Bl[128 * SMSTRIDE];

    float C[2][8][4];
#pragma unroll
    for (int mt = 0; mt < 2; mt++)
#pragma unroll
        for (int nt = 0; nt < 8; nt++)
#pragma unroll
            for (int r = 0; r < 4; r++) C[mt][nt][r] = 0.f;

    const uint32_t uAh = s2u(Ah), uAl = s2u(Al), uBh = s2u(Bh), uBl = s2u(Bl);
    const int g = lane >> 2;
    const int qp = lane & 3;
    const int frow = lane & 15;              // fragment row within 16
    const int fcol = (lane >> 4) << 3;       // 0 or 8

    for (int k0 = 0; k0 < KDIM; k0 += 32) {
        // load + split
#pragma unroll
        for (int t = 0; t < 4; t++) {
            int l = tid + t * 256;
            int row = l >> 3;
            int kc = (l & 7) * 4;
            float4 av = *(const float4*)&A[(size_t)(m0 + row) * KDIM + k0 + kc];
            float4 bv = *(const float4*)&W[(size_t)(n0 + row) * KDIM + k0 + kc];
            float af[4] = {av.x, av.y, av.z, av.w};
            float bf[4] = {bv.x, bv.y, bv.z, bv.w};
            float ahf[4], alf[4], bhf[4], blf[4];
#pragma unroll
            for (int e = 0; e < 4; e++) {
                __nv_bfloat16 ah = __float2bfloat16(af[e]);
                __nv_bfloat16 bh = __float2bfloat16(bf[e]);
                ahf[e] = __bfloat162float(ah);
                bhf[e] = __bfloat162float(bh);
                alf[e] = af[e] - ahf[e];
                blf[e] = bf[e] - bhf[e];
            }
            uint32_t* pAh = (uint32_t*)&Ah[row * SMSTRIDE + kc];
            uint32_t* pAl = (uint32_t*)&Al[row * SMSTRIDE + kc];
            uint32_t* pBh = (uint32_t*)&Bh[row * SMSTRIDE + kc];
            uint32_t* pBl = (uint32_t*)&Bl[row * SMSTRIDE + kc];
            pAh[0] = packbf(ahf[0], ahf[1]); pAh[1] = packbf(ahf[2], ahf[3]);
            pAl[0] = packbf(alf[0], alf[1]); pAl[1] = packbf(alf[2], alf[3]);
            pBh[0] = packbf(bhf[0], bhf[1]); pBh[1] = packbf(bhf[2], bhf[3]);
            pBl[0] = packbf(blf[0], blf[1]); pBl[1] = packbf(blf[2], blf[3]);
        }
        __syncthreads();

#pragma unroll
        for (int kc = 0; kc < 2; kc++) {
            const int col = kc * 16 + fcol;
            uint32_t a_hi[2][4], a_lo[2][4];
#pragma unroll
            for (int mt = 0; mt < 2; mt++) {
                uint32_t off = ((warpM * 32 + mt * 16 + frow) * SMSTRIDE + col) * 2;
                LDSM_X4(a_hi[mt], uAh + off);
                LDSM_X4(a_lo[mt], uAl + off);
            }
#pragma unroll
            for (int p = 0; p < 4; p++) {
                uint32_t off = ((warpN * 64 + p * 16 + frow) * SMSTRIDE + col) * 2;
                uint32_t kb_h[4], kb_l[4];
                LDSM_X4(kb_h, uBh + off);
                LDSM_X4(kb_l, uBl + off);
                uint32_t bh0[2] = {kb_h[0], kb_h[2]};
                uint32_t bh1[2] = {kb_h[1], kb_h[3]};
                uint32_t bl0[2] = {kb_l[0], kb_l[2]};
                uint32_t bl1[2] = {kb_l[1], kb_l[3]};
#pragma unroll
                for (int mt = 0; mt < 2; mt++) {
                    MMA_BF16(C[mt][2 * p], a_hi[mt], bh0);
                    MMA_BF16(C[mt][2 * p], a_lo[mt], bh0);
                    MMA_BF16(C[mt][2 * p], a_hi[mt], bl0);
                    MMA_BF16(C[mt][2 * p + 1], a_hi[mt], bh1);
                    MMA_BF16(C[mt][2 * p + 1], a_lo[mt], bh1);
                    MMA_BF16(C[mt][2 * p + 1], a_hi[mt], bl1);
                }
            }
        }
        __syncthreads();
    }

    // epilogue
#pragma unroll
    for (int mt = 0; mt < 2; mt++) {
#pragma unroll
        for (int nt = 0; nt < 8; nt++) {
            int gm0 = m0 + warpM * 32 + mt * 16 + g;
            int gn = n0 + warpN * 64 + nt * 8 + qp * 2;
            float2 v0 = make_float2(C[mt][nt][0], C[mt][nt][1]);
            float2 v1 = make_float2(C[mt][nt][2], C[mt][nt][3]);
            if (MODE == 0) {
                int which = gn >> 11;
                int rem = gn & 2047;
                int h = rem >> 7;
                int d = rem & 127;
#pragma unroll
                for (int rr = 0; rr < 2; rr++) {
                    int gm = gm0 + rr * 8;
                    int b = gm >> 11;
                    int s = gm & 2047;
                    size_t off = (size_t)which * ((size_t)B_ * NH_ * S_ * HD_) +
                                 (((size_t)(b * NH_ + h)) * S_ + s) * HD_ + d;
                    *(float2*)&g_qkv[off] = rr ? v1 : v0;
                }
            } else {
                *(float2*)&Cout[(size_t)gm0 * HID_ + gn] = v0;
                *(float2*)&Cout[(size_t)(gm0 + 8) * HID_ + gn] = v1;
            }
        }
    }
}

// ---------------------------------------------------------------------------
// RoPE in-place on Q and K halves of g_qkv.
// ---------------------------------------------------------------------------
__global__ __launch_bounds__(256)
void rope_kernel(const float* __restrict__ cosT, const float* __restrict__ sinT) {
    long long t = (long long)blockIdx.x * 256 + threadIdx.x;
    int d = (int)(t & 63);
    long long row = t >> 6;
    int s = (int)(row % S_);
    float* p = g_qkv + row * HD_;
    float x1 = p[d];
    float x2 = p[d + 64];
    float c1 = cosT[s * HD_ + d];
    float s1 = sinT[s * HD_ + d];
    float c2 = cosT[s * HD_ + d + 64];
    float s2 = sinT[s * HD_ + d + 64];
    p[d]      = x1 * c1 - x2 * s1;
    p[d + 64] = x2 * c2 + x1 * s2;
}

// ---------------------------------------------------------------------------
// Split-bf16 tensor-core causal flash attention.
// BQ=128 (8 warps x 16 rows), BK=64, 256 threads.
// ---------------------------------------------------------------------------
#define STQ 136   // bf16 row stride (128 + 8 pad); 272B = 17*16B, row step = 4 banks

#define ATTN_SMEM ((2 * 128 + 4 * 64) * STQ * 2)   // 139264 bytes

__global__ __launch_bounds__(256, 1)
void attn_mma_kernel() {
    extern __shared__ char smraw[];
    __nv_bfloat16* sQh = (__nv_bfloat16*)smraw;
    __nv_bfloat16* sQl = sQh + 128 * STQ;
    __nv_bfloat16* sKh = sQl + 128 * STQ;
    __nv_bfloat16* sKl = sKh + 64 * STQ;
    __nv_bfloat16* sVh = sKl + 64 * STQ;
    __nv_bfloat16* sVl = sVh + 64 * STQ;

    const int tid = threadIdx.x;
    const int lane = tid & 31;
    const int w = tid >> 5;
    const int qp = lane & 3;
    const int g = lane >> 2;
    const int frow = lane & 15;
    const int fcol = (lane >> 4) << 3;

    const int qt = blockIdx.x;
    const int bh = blockIdx.y;
    const int b = bh >> 4;
    const int h = bh & 15;
    const int q0 = qt * 128;

    const size_t hs = (size_t)S_ * HD_;
    const float* Qg = g_qkv + (size_t)bh * hs;
    const float* Kg = g_qkv + (size_t)(B_ * NH_ + bh) * hs;
    const float* Vg = g_qkv + (size_t)(2 * B_ * NH_ + bh) * hs;

    // ---- load Q tile (128 x 128), split to hi/lo bf16 ----
#pragma unroll
    for (int i = 0; i < 16; i++) {
        int idx = tid + i * 256;          // 0..4095
        int r = idx >> 5;
        int d = (idx & 31) << 2;
        float4 v = *(const float4*)&Qg[(size_t)(q0 + r) * HD_ + d];
        float f[4] = {v.x, v.y, v.z, v.w};
        float hf[4], lf[4];
#pragma unroll
        for (int e = 0; e < 4; e++) {
            hf[e] = __bfloat162float(__float2bfloat16(f[e]));
            lf[e] = f[e] - hf[e];
        }
        uint32_t* ph = (uint32_t*)&sQh[r * STQ + d];
        uint32_t* pl = (uint32_t*)&sQl[r * STQ + d];
        ph[0] = packbf(hf[0], hf[1]); ph[1] = packbf(hf[2], hf[3]);
        pl[0] = packbf(lf[0], lf[1]); pl[1] = packbf(lf[2], lf[3]);
    }

    const uint32_t uQh = s2u(sQh), uQl = s2u(sQl);
    const uint32_t uKh = s2u(sKh), uKl = s2u(sKl);
    const uint32_t uVh = s2u(sVh), uVl = s2u(sVl);

    float O[16][4];
#pragma unroll
    for (int t = 0; t < 16; t++)
#pragma unroll
        for (int r = 0; r < 4; r++) O[t][r] = 0.f;
    float m0 = -1e30f, m1 = -1e30f, l0 = 0.f, l1 = 0.f;

    const float sc = 0.08838834764831845f;
    const int row0 = q0 + w * 16 + g;
    const int row1 = row0 + 8;

    __syncthreads();

    const int ktn = (q0 + 128) >> 6;
    for (int kt = 0; kt < ktn; kt++) {
        const int k0 = kt * 64;
        // ---- load K,V tiles (64 x 128 each), split ----
#pragma unroll
        for (int i = 0; i < 8; i++) {
            int idx = tid + i * 256;      // 0..2047
            int r = idx >> 5;
            int d = (idx & 31) << 2;
            float4 kv = *(const float4*)&Kg[(size_t)(k0 + r) * HD_ + d];
            float4 vv = *(const float4*)&Vg[(size_t)(k0 + r) * HD_ + d];
            float kf[4] = {kv.x, kv.y, kv.z, kv.w};
            float vf[4] = {vv.x, vv.y, vv.z, vv.w};
            float khf[4], klf[4], vhf[4], vlf[4];
#pragma unroll
            for (int e = 0; e < 4; e++) {
                khf[e] = __bfloat162float(__float2bfloat16(kf[e]));
                klf[e] = kf[e] - khf[e];
                vhf[e] = __bfloat162float(__float2bfloat16(vf[e]));
                vlf[e] = vf[e] - vhf[e];
            }
            uint32_t* pkh = (uint32_t*)&sKh[r * STQ + d];
            uint32_t* pkl = (uint32_t*)&sKl[r * STQ + d];
            uint32_t* pvh = (uint32_t*)&sVh[r * STQ + d];
            uint32_t* pvl = (uint32_t*)&sVl[r * STQ + d];
            pkh[0] = packbf(khf[0], khf[1]); pkh[1] = packbf(khf[2], khf[3]);
            pkl[0] = packbf(klf[0], klf[1]); pkl[1] = packbf(klf[2], klf[3]);
            pvh[0] = packbf(vhf[0], vhf[1]); pvh[1] = packbf(vhf[2], vhf[3]);
            pvl[0] = packbf(vlf[0], vlf[1]); pvl[1] = packbf(vlf[2], vlf[3]);
        }
        __syncthreads();

        const bool active = (k0 <= q0 + w * 16 + 15);
        if (active) {
            // ---- S = Q K^T ----
            float S[8][4];
#pragma unroll
            for (int t = 0; t < 8; t++)
#pragma unroll
                for (int r = 0; r < 4; r++) S[t][r] = 0.f;

#pragma unroll
            for (int kc = 0; kc < 8; kc++) {
                const int col = kc * 16 + fcol;
                uint32_t qh[4], ql[4];
                uint32_t qoff = ((w * 16 + frow) * STQ + col) * 2;
                LDSM_X4(qh, uQh + qoff);
                LDSM_X4(ql, uQl + qoff);
#pragma unroll
                for (int p = 0; p < 4; p++) {
                    uint32_t koff = ((p * 16 + frow) * STQ + col) * 2;
                    uint32_t kh[4], kl[4];
                    LDSM_X4(kh, uKh + koff);
                    LDSM_X4(kl, uKl + koff);
                    uint32_t bh0[2] = {kh[0], kh[2]};
                    uint32_t bh1[2] = {kh[1], kh[3]};
                    uint32_t bl0[2] = {kl[0], kl[2]};
                    uint32_t bl1[2] = {kl[1], kl[3]};
                    MMA_BF16(S[2 * p], qh, bh0);
                    MMA_BF16(S[2 * p], ql, bh0);
                    MMA_BF16(S[2 * p], qh, bl0);
                    MMA_BF16(S[2 * p + 1], qh, bh1);
                    MMA_BF16(S[2 * p + 1], ql, bh1);
                    MMA_BF16(S[2 * p + 1], qh, bl1);
                }
            }

            // ---- scale + causal mask ----
            const bool maskneed = (k0 + 63 > row0);
#pragma unroll
            for (int t = 0; t < 8; t++) {
                int c0 = k0 + 8 * t + 2 * qp;
#pragma unroll
                for (int r = 0; r < 4; r++) {
                    S[t][r] *= sc;
                    if (maskneed) {
                        int colg = c0 + (r & 1);
                        int rowg = (r < 2) ? row0 : row1;
                        if (colg > rowg) S[t][r] = -1e9f;
                    }
                }
            }

            // ---- online softmax (rows g, g+8) ----
            float rm0 = -1e30f, rm1 = -1e30f;
#pragma unroll
            for (int t = 0; t < 8; t++) {
                rm0 = fmaxf(rm0, fmaxf(S[t][0], S[t][1]));
                rm1 = fmaxf(rm1, fmaxf(S[t][2], S[t][3]));
            }
            rm0 = fmaxf(rm0, __shfl_xor_sync(0xffffffffu, rm0, 1));
            rm0 = fmaxf(rm0, __shfl_xor_sync(0xffffffffu, rm0, 2));
            rm1 = fmaxf(rm1, __shfl_xor_sync(0xffffffffu, rm1, 1));
            rm1 = fmaxf(rm1, __shfl_xor_sync(0xffffffffu, rm1, 2));
            float mn0 = fmaxf(m0, rm0), mn1 = fmaxf(m1, rm1);
            float a0 = __expf(m0 - mn0), a1 = __expf(m1 - mn1);
            float rs0 = 0.f, rs1 = 0.f;
#pragma unroll
            for (int t = 0; t < 8; t++) {
                S[t][0] = __expf(S[t][0] - mn0);
                S[t][1] = __expf(S[t][1] - mn0);
                S[t][2] = __expf(S[t][2] - mn1);
                S[t][3] = __expf(S[t][3] - mn1);
                rs0 += S[t][0] + S[t][1];
                rs1 += S[t][2] + S[t][3];
            }
            rs0 += __shfl_xor_sync(0xffffffffu, rs0, 1);
            rs0 += __shfl_xor_sync(0xffffffffu, rs0, 2);
            rs1 += __shfl_xor_sync(0xffffffffu, rs1, 1);
            rs1 += __shfl_xor_sync(0xffffffffu, rs1, 2);
            l0 = l0 * a0 + rs0;
            l1 = l1 * a1 + rs1;
            m0 = mn0;
            m1 = mn1;
#pragma unroll
            for (int t = 0; t < 16; t++) {
                O[t][0] *= a0; O[t][1] *= a0;
                O[t][2] *= a1; O[t][3] *= a1;
            }

            // ---- P fragments (hi/lo) in-register ----
            uint32_t ph[4][4], pl[4][4];
#pragma unroll
            for (int kc2 = 0; kc2 < 4; kc2++) {
                int t0 = 2 * kc2, t1 = 2 * kc2 + 1;
                float hv[8], lv[8];
                float src[8] = {S[t0][0], S[t0][1], S[t0][2], S[t0][3],
                                S[t1][0], S[t1][1], S[t1][2], S[t1][3]};
#pragma unroll
                for (int e = 0; e < 8; e++) {
                    hv[e] = __bfloat162float(__float2bfloat16(src[e]));
                    lv[e] = src[e] - hv[e];
                }
                ph[kc2][0] = packbf(hv[0], hv[1]);  // (g, k 2qp..) of t0
                ph[kc2][1] = packbf(hv[2], hv[3]);  // (g+8, ..) of t0
                ph[kc2][2] = packbf(hv[4], hv[5]);  // (g, ..) of t1
                ph[kc2][3] = packbf(hv[6], hv[7]);  // (g+8, ..) of t1
                pl[kc2][0] = packbf(lv[0], lv[1]);
                pl[kc2][1] = packbf(lv[2], lv[3]);
                pl[kc2][2] = packbf(lv[4], lv[5]);
                pl[kc2][3] = packbf(lv[6], lv[7]);
            }

            // ---- O += P V  (V via ldmatrix.trans) ----
#pragma unroll
            for (int kc2 = 0; kc2 < 4; kc2++) {
#pragma unroll
                for (int p = 0; p < 8; p++) {
                    uint32_t voff = ((kc2 * 16 + frow) * STQ + p * 16 + fcol) * 2;
                    uint32_t vh[4], vl[4];
                    LDSM_X4T(vh, uVh + voff);
                    LDSM_X4T(vl, uVl + voff);
                    uint32_t bh0[2] = {vh[0], vh[1]};
                    uint32_t bh1[2] = {vh[2], vh[3]};
                    uint32_t bl0[2] = {vl[0], vl[1]};
                    uint32_t bl1[2] = {vl[2], vl[3]};
                    MMA_BF16(O[2 * p], ph[kc2], bh0);
                    MMA_BF16(O[2 * p], pl[kc2], bh0);
                    MMA_BF16(O[2 * p], ph[kc2], bl0);
                    MMA_BF16(O[2 * p + 1], ph[kc2], bh1);
                    MMA_BF16(O[2 * p + 1], pl[kc2], bh1);
                    MMA_BF16(O[2 * p + 1], ph[kc2], bl1);
                }
            }
        }
        __syncthreads();
    }

    // ---- normalize + write ctx [b][s][h][d] ----
    float inv0 = 1.f / l0, inv1 = 1.f / l1;
    size_t base0 = (((size_t)b * S_ + row0) * NH_ + h) * HD_;
    size_t base1 = (((size_t)b * S_ + row1) * NH_ + h) * HD_;
#pragma unroll
    for (int t = 0; t < 16; t++) {
        int d = 8 * t + 2 * qp;
        *(float2*)&g_ctx[base0 + d] = make_float2(O[t][0] * inv0, O[t][1] * inv0);
        *(float2*)&g_ctx[base1 + d] = make_float2(O[t][2] * inv1, O[t][3] * inv1);
    }
}

// ---------------------------------------------------------------------------
extern "C" void kernel_launch(void* const* d_in, const int* in_sizes, int n_in,
                              void* d_out, int out_size) {
    (void)in_sizes; (void)n_in; (void)out_size;
    const float* x     = (const float*)d_in[0];
    const float* w_qkv = (const float*)d_in[1];
    const float* w_o   = (const float*)d_in[2];
    const float* cosT  = (const float*)d_in[3];
    const float* sinT  = (const float*)d_in[4];
    float* out = (float*)d_out;

    cudaFuncSetAttribute(attn_mma_kernel, cudaFuncAttributeMaxDynamicSharedMemorySize, ATTN_SMEM);

    gemm_bf16_kernel<0><<<dim3(6144 / 128, 4096 / 128), 256>>>(x, w_qkv, nullptr);
    rope_kernel<<<(2 * B_ * NH_ * S_ * 64) / 256, 256>>>(cosT, sinT);
    attn_mma_kernel<<<dim3(S_ / 128, B_ * NH_), 256, ATTN_SMEM>>>();
    gemm_bf16_kernel<1><<<dim3(2048 / 128, 4096 / 128), 256>>>(nullptr, w_o, out);
}